// round 4
// baseline (speedup 1.0000x reference)
#include <cuda_runtime.h>
#include <math.h>

// Problem constants: B=16384, A=50, D=256, alpha=0.2
constexpr int Bn = 16384;
constexpr int An = 50;
constexpr int Dn = 256;
constexpr float ALPHA = 0.2f;

constexpr int NT = 512;                 // 16 warps per CTA
constexpr int D4 = Dn / 4;              // 64 float4 per row

__global__ __launch_bounds__(NT, 2)
void struct_attention_kernel(const float* __restrict__ attrs,   // [B, A, D]
                             const float* __restrict__ ent,     // [B, D]
                             const float* __restrict__ avec,    // [2D, 1]
                             float* __restrict__ out)           // [B, D]
{
    // smem: cross-warp partial buffer (16 KB) + score staging
    __shared__ float4 part4[16 * D4];   // [warp][d4]
    __shared__ float  e_s[64];          // 51 used: [0..49] attr scores, [50] entity bias

    const int b    = blockIdx.x;
    const int t    = threadIdx.x;
    const int w    = t >> 5;            // 0..15, warp-uniform
    const int lane = t & 31;

    const float4* a4     = reinterpret_cast<const float4*>(avec);            // [0,64)=a_attr, [64,128)=a_ent
    const float4* attrs4 = reinterpret_cast<const float4*>(attrs) + (size_t)b * (An * D4);
    const float4* ent4   = reinterpret_cast<const float4*>(ent)   + (size_t)b * D4;

    // ---- Front-batched loads: branch-free / warp-uniform -----------------
    // Warp w owns rows a = w, w+16, w+32 (w+32 <= 47 < 50, always valid),
    // plus 4th row: a = 48+w for w<2 (attrs), entity "row" for w==2.
    const float4 aa0 = __ldg(a4 + lane);
    const float4 aa1 = __ldg(a4 + 32 + lane);

    const float4* r0 = attrs4 + (size_t)(w)      * D4;
    const float4* r1 = attrs4 + (size_t)(w + 16) * D4;
    const float4* r2 = attrs4 + (size_t)(w + 32) * D4;

    float4 v00 = __ldg(r0 + lane), v01 = __ldg(r0 + 32 + lane);
    float4 v10 = __ldg(r1 + lane), v11 = __ldg(r1 + 32 + lane);
    float4 v20 = __ldg(r2 + lane), v21 = __ldg(r2 + 32 + lane);

    const bool has3  = (w < 3);         // warp-uniform branches: convergent
    const bool isent = (w == 2);

    auto dot8 = [](const float4& x0, const float4& x1,
                   const float4& y0, const float4& y1) -> float {
        return x0.x*y0.x + x0.y*y0.y + x0.z*y0.z + x0.w*y0.w
             + x1.x*y1.x + x1.y*y1.y + x1.z*y1.z + x1.w*y1.w;
    };

    // ---- Pass 1: per-row dot products --------------------------------
    float p0 = dot8(v00, v01, aa0, aa1);
    float p1 = dot8(v10, v11, aa0, aa1);
    float p2 = dot8(v20, v21, aa0, aa1);

    float4 v30 = make_float4(0.f, 0.f, 0.f, 0.f), v31 = v30;
    float p3 = 0.f;
    if (has3) {
        const float4* r3 = isent ? ent4 : (attrs4 + (size_t)(48 + w) * D4);
        v30 = __ldg(r3 + lane);
        v31 = __ldg(r3 + 32 + lane);
        if (isent) {
            // entity row dots against a_ent; coeff regs die immediately
            const float4 ce0 = __ldg(a4 + 64 + lane);
            const float4 ce1 = __ldg(a4 + 96 + lane);
            p3 = dot8(v30, v31, ce0, ce1);
        } else {
            p3 = dot8(v30, v31, aa0, aa1);
        }
    }

#pragma unroll
    for (int off = 16; off; off >>= 1) {
        p0 += __shfl_xor_sync(0xffffffffu, p0, off);
        p1 += __shfl_xor_sync(0xffffffffu, p1, off);
        p2 += __shfl_xor_sync(0xffffffffu, p2, off);
        p3 += __shfl_xor_sync(0xffffffffu, p3, off);
    }
    if (lane == 0) {
        e_s[w]      = p0;
        e_s[w + 16] = p1;
        e_s[w + 32] = p2;
        if (has3) e_s[isent ? 50 : (48 + w)] = p3;   // w==2 -> entity bias
    }
    __syncthreads();

    // ---- Softmax (recomputed by every warp; removes a barrier) ----------
    const float bias = e_s[An];                       // broadcast LDS
    float e0 = (lane      < An) ? e_s[lane]      + bias : -INFINITY;
    float e1 = (lane + 32 < An) ? e_s[lane + 32] + bias : -INFINITY;
    e0 = (e0 > 0.f) ? e0 : ALPHA * e0;                // leaky_relu; -inf stays -inf
    e1 = (e1 > 0.f) ? e1 : ALPHA * e1;

    float m = fmaxf(e0, e1);
#pragma unroll
    for (int off = 16; off; off >>= 1)
        m = fmaxf(m, __shfl_xor_sync(0xffffffffu, m, off));
    float q0 = __expf(e0 - m);                        // exp(-inf) = 0 for masked lanes
    float q1 = __expf(e1 - m);
    float s = q0 + q1;
#pragma unroll
    for (int off = 16; off; off >>= 1)
        s += __shfl_xor_sync(0xffffffffu, s, off);
    const float scale = (float)An / s;                // softmax * attr_num

    auto attw = [&](int a) -> float {                 // attention weight for row a
        float ea = e_s[a] + bias;
        ea = (ea > 0.f) ? ea : ALPHA * ea;
        return __expf(ea - m) * scale;
    };

    // ---- Pass 2: weighted sum from registers -----------------------------
    const float att0 = attw(w);
    const float att1 = attw(w + 16);
    const float att2 = attw(w + 32);

    float4 acc0, acc1;
    acc0.x = att0*v00.x; acc0.y = att0*v00.y; acc0.z = att0*v00.z; acc0.w = att0*v00.w;
    acc1.x = att0*v01.x; acc1.y = att0*v01.y; acc1.z = att0*v01.z; acc1.w = att0*v01.w;
    acc0.x = fmaf(att1, v10.x, acc0.x); acc0.y = fmaf(att1, v10.y, acc0.y);
    acc0.z = fmaf(att1, v10.z, acc0.z); acc0.w = fmaf(att1, v10.w, acc0.w);
    acc1.x = fmaf(att1, v11.x, acc1.x); acc1.y = fmaf(att1, v11.y, acc1.y);
    acc1.z = fmaf(att1, v11.z, acc1.z); acc1.w = fmaf(att1, v11.w, acc1.w);
    acc0.x = fmaf(att2, v20.x, acc0.x); acc0.y = fmaf(att2, v20.y, acc0.y);
    acc0.z = fmaf(att2, v20.z, acc0.z); acc0.w = fmaf(att2, v20.w, acc0.w);
    acc1.x = fmaf(att2, v21.x, acc1.x); acc1.y = fmaf(att2, v21.y, acc1.y);
    acc1.z = fmaf(att2, v21.z, acc1.z); acc1.w = fmaf(att2, v21.w, acc1.w);
    if (w < 2) {                                      // 4th attr row; entity row excluded
        const float att3 = attw(48 + w);
        acc0.x = fmaf(att3, v30.x, acc0.x); acc0.y = fmaf(att3, v30.y, acc0.y);
        acc0.z = fmaf(att3, v30.z, acc0.z); acc0.w = fmaf(att3, v30.w, acc0.w);
        acc1.x = fmaf(att3, v31.x, acc1.x); acc1.y = fmaf(att3, v31.y, acc1.y);
        acc1.z = fmaf(att3, v31.z, acc1.z); acc1.w = fmaf(att3, v31.w, acc1.w);
    }

    // cross-warp reduction: 16 KB through smem, then 64-thread final sum
    part4[w * D4 + lane]      = acc0;   // d = 4*lane
    part4[w * D4 + 32 + lane] = acc1;   // d = 128 + 4*lane
    __syncthreads();

    if (t < D4) {
        float4 sum = part4[t];
#pragma unroll
        for (int ww = 1; ww < 16; ww++) {
            const float4 v = part4[ww * D4 + t];
            sum.x += v.x; sum.y += v.y; sum.z += v.z; sum.w += v.w;
        }
        reinterpret_cast<float4*>(out)[(size_t)b * D4 + t] = sum;
    }
}

extern "C" void kernel_launch(void* const* d_in, const int* in_sizes, int n_in,
                              void* d_out, int out_size)
{
    const float* attrs = (const float*)d_in[0];   // [B, A, D] fp32
    const float* ent   = (const float*)d_in[1];   // [B, D]    fp32
    const float* avec  = (const float*)d_in[2];   // [2D, 1]   fp32
    float* out         = (float*)d_out;           // [B, D]    fp32

    struct_attention_kernel<<<Bn, NT>>>(attrs, ent, avec, out);
}

// round 7
// speedup vs baseline: 1.0919x; 1.0919x over previous
#include <cuda_runtime.h>
#include <math.h>

// Problem constants: B=16384, A=50, D=256, alpha=0.2
constexpr int Bn = 16384;
constexpr int An = 50;
constexpr int Dn = 256;
constexpr float ALPHA = 0.2f;

constexpr int NTHREADS = 256;           // 8 warps
constexpr int D4 = Dn / 4;              // 64
// smem layout: tile[An*Dn] fp32, then e[64], then att[64]
constexpr int SMEM_TILE_FLOATS = An * Dn;            // 12800
constexpr int SMEM_FLOATS = SMEM_TILE_FLOATS + 64 + 64;
constexpr int SMEM_BYTES = SMEM_FLOATS * (int)sizeof(float);  // 51712

__global__ __launch_bounds__(NTHREADS, 4)
void struct_attention_kernel(const float* __restrict__ attrs,   // [B, A, D]
                             const float* __restrict__ ent,     // [B, D]
                             const float* __restrict__ avec,    // [2D, 1]
                             float* __restrict__ out)           // [B, D]
{
    extern __shared__ float smem[];
    float*  tile  = smem;                        // An*Dn
    float*  e_s   = smem + SMEM_TILE_FLOATS;     // 64 slots (uses 51)
    float*  att_s = e_s + 64;                    // 64 slots (uses 50)
    float4* tile4 = reinterpret_cast<float4*>(tile);

    const int b    = blockIdx.x;
    const int t    = threadIdx.x;
    const int w    = t >> 5;                     // 0..7, warp-uniform
    const int lane = t & 31;

    const float4* a4     = reinterpret_cast<const float4*>(avec);  // [0,64)=a_attr, [64,128)=a_ent
    const float4* attrs4 = reinterpret_cast<const float4*>(attrs) + (size_t)b * (An * D4);
    const float4* ent4   = reinterpret_cast<const float4*>(ent)   + (size_t)b * D4;

    const float4 aa0 = __ldg(a4 + lane);
    const float4 aa1 = __ldg(a4 + 32 + lane);

    auto dot8 = [](const float4& x0, const float4& x1,
                   const float4& y0, const float4& y1) -> float {
        return x0.x*y0.x + x0.y*y0.y + x0.z*y0.z + x0.w*y0.w
             + x1.x*y1.x + x1.y*y1.y + x1.z*y1.z + x1.w*y1.w;
    };

    // ---- Pass 1: stage tile + per-thread dot partials (NO shfl yet) -----
    // Warp w owns rows a = w + 8k. k=0..5 always valid (a <= 47 < 50);
    // k=6 tail: a = 48+w -> rows 48,49 (w=0,1), entity "row" (w==2).
    float p[7];
#pragma unroll
    for (int k = 0; k < 6; k++) {
        const int a = w + 8 * k;
        const float4* row = attrs4 + (size_t)a * D4;
        const float4 v0 = __ldg(row + lane);
        const float4 v1 = __ldg(row + 32 + lane);
        p[k] = dot8(v0, v1, aa0, aa1);
        tile4[a * D4 + lane]      = v0;
        tile4[a * D4 + 32 + lane] = v1;
    }
    p[6] = 0.f;
    if (w < 3) {                                 // warp-uniform, convergent
        const bool isent = (w == 2);
        const float4* r3 = isent ? ent4 : (attrs4 + (size_t)(48 + w) * D4);
        const float4 v0 = __ldg(r3 + lane);
        const float4 v1 = __ldg(r3 + 32 + lane);
        if (isent) {
            const float4 ce0 = __ldg(a4 + 64 + lane);
            const float4 ce1 = __ldg(a4 + 96 + lane);
            p[6] = dot8(v0, v1, ce0, ce1);
        } else {
            p[6] = dot8(v0, v1, aa0, aa1);
            tile4[(48 + w) * D4 + lane]      = v0;
            tile4[(48 + w) * D4 + 32 + lane] = v1;
        }
    }

    // ---- Batched warp reductions: 7 independent values, 5 rounds --------
    // Shfls within a round are independent -> latency ~5*(7 issue + 26)
    // instead of 7 serial ~130-cycle chains.
#pragma unroll
    for (int off = 16; off; off >>= 1) {
#pragma unroll
        for (int k = 0; k < 7; k++)
            p[k] += __shfl_xor_sync(0xffffffffu, p[k], off);
    }
    if (lane == 0) {
#pragma unroll
        for (int k = 0; k < 6; k++)
            e_s[w + 8 * k] = p[k];
        if (w < 3) e_s[(w == 2) ? 50 : (48 + w)] = p[6];  // w==2 -> entity bias
    }
    __syncthreads();

    // ---- Softmax over 50 scores (single warp) ---------------------------
    if (w == 0) {
        const float bias = e_s[An];
        float e0 = (lane      < An) ? e_s[lane]      + bias : -INFINITY;
        float e1 = (lane + 32 < An) ? e_s[lane + 32] + bias : -INFINITY;
        e0 = (e0 > 0.f) ? e0 : ALPHA * e0;       // leaky_relu; -inf stays -inf
        e1 = (e1 > 0.f) ? e1 : ALPHA * e1;

        float m = fmaxf(e0, e1);
#pragma unroll
        for (int off = 16; off; off >>= 1)
            m = fmaxf(m, __shfl_xor_sync(0xffffffffu, m, off));
        float q0 = __expf(e0 - m);               // exp(-inf)=0 for masked lanes
        float q1 = __expf(e1 - m);
        float s = q0 + q1;
#pragma unroll
        for (int off = 16; off; off >>= 1)
            s += __shfl_xor_sync(0xffffffffu, s, off);

        const float scale = (float)An / s;       // softmax * attr_num
        if (lane      < An) att_s[lane]      = q0 * scale;
        if (lane + 32 < An) att_s[lane + 32] = q1 * scale;
    }
    __syncthreads();

    // ---- Pass 2: out[b, d] = sum_a att[a] * tile[a, d] ------------------
    // Threads 0..63 each own one float4 column group; consecutive threads
    // hit consecutive 16B -> conflict-free LDS.128 + broadcast LDS.
    if (t < D4) {
        float4 acc = make_float4(0.f, 0.f, 0.f, 0.f);
#pragma unroll
        for (int a = 0; a < An; a++) {
            const float att = att_s[a];
            const float4 v  = tile4[a * D4 + t];
            acc.x = fmaf(att, v.x, acc.x);
            acc.y = fmaf(att, v.y, acc.y);
            acc.z = fmaf(att, v.z, acc.z);
            acc.w = fmaf(att, v.w, acc.w);
        }
        reinterpret_cast<float4*>(out)[(size_t)b * D4 + t] = acc;
    }
}

extern "C" void kernel_launch(void* const* d_in, const int* in_sizes, int n_in,
                              void* d_out, int out_size)
{
    const float* attrs = (const float*)d_in[0];   // [B, A, D] fp32
    const float* ent   = (const float*)d_in[1];   // [B, D]    fp32
    const float* avec  = (const float*)d_in[2];   // [2D, 1]   fp32
    float* out         = (float*)d_out;           // [B, D]    fp32

    // 51.7 KB dynamic smem (> 48 KB static limit); attribute set is
    // idempotent and graph-capture safe.
    cudaFuncSetAttribute(struct_attention_kernel,
                         cudaFuncAttributeMaxDynamicSharedMemorySize, SMEM_BYTES);

    struct_attention_kernel<<<Bn, NTHREADS, SMEM_BYTES>>>(attrs, ent, avec, out);
}

// round 8
// speedup vs baseline: 1.3988x; 1.2811x over previous
#include <cuda_runtime.h>
#include <cstdint>
#include <math.h>

// Problem constants: B=16384, A=50, D=256, alpha=0.2
constexpr int Bn = 16384;
constexpr int An = 50;
constexpr int Dn = 256;
constexpr float ALPHA = 0.2f;

constexpr int NTHREADS = 256;              // 8 warps
constexpr int D4 = Dn / 4;                 // 64
constexpr int ROWS_T = An + 1;             // 51 rows: 50 attrs + entity row
constexpr int TILE_FLOATS = ROWS_T * Dn;   // 13056
constexpr int ATTR_BYTES = An * Dn * 4;    // 51200 (contiguous per b)
constexpr int ENT_BYTES  = Dn * 4;         // 1024
// dynamic smem: tile[13056] + e_s[64] + att_s[64] + mbar (16B aligned)
constexpr int SMEM_FLOATS = TILE_FLOATS + 64 + 64 + 8;
constexpr int SMEM_BYTES  = SMEM_FLOATS * (int)sizeof(float);   // ~52.8 KB

__device__ __forceinline__ uint32_t smem_u32(const void* p) {
    uint32_t a;
    asm("{ .reg .u64 t; cvta.to.shared.u64 t, %1; cvt.u32.u64 %0, t; }"
        : "=r"(a) : "l"(p));
    return a;
}

__global__ __launch_bounds__(NTHREADS, 4)
void struct_attention_kernel(const float* __restrict__ attrs,   // [B, A, D]
                             const float* __restrict__ ent,     // [B, D]
                             const float* __restrict__ avec,    // [2D, 1]
                             float* __restrict__ out)           // [B, D]
{
    extern __shared__ float smem[];
    float*  tile  = smem;                        // 51 rows x 256
    float*  e_s   = smem + TILE_FLOATS;          // 64 slots (uses 51)
    float*  att_s = e_s + 64;                    // 64 slots (uses 50)
    unsigned long long* mbar = reinterpret_cast<unsigned long long*>(att_s + 64);
    float4* tile4 = reinterpret_cast<float4*>(tile);

    const int b    = blockIdx.x;
    const int t    = threadIdx.x;
    const int w    = t >> 5;                     // 0..7, warp-uniform
    const int lane = t & 31;

    const uint32_t mbar_a = smem_u32(mbar);
    const uint32_t tile_a = smem_u32(tile);

    // ---- TMA bulk load: whole attrs[b] tile + entity row, one mbarrier ----
    if (t == 0) {
        asm volatile("mbarrier.init.shared.b64 [%0], 1;" :: "r"(mbar_a) : "memory");
    }
    __syncthreads();
    if (t == 0) {
        asm volatile("mbarrier.arrive.expect_tx.shared.b64 _, [%0], %1;"
                     :: "r"(mbar_a), "r"((uint32_t)(ATTR_BYTES + ENT_BYTES)) : "memory");
        const float* srcA = attrs + (size_t)b * (An * Dn);
        const float* srcE = ent   + (size_t)b * Dn;
        asm volatile("cp.async.bulk.shared::cta.global.mbarrier::complete_tx::bytes "
                     "[%0], [%1], %2, [%3];"
                     :: "r"(tile_a), "l"(srcA), "r"((uint32_t)ATTR_BYTES), "r"(mbar_a)
                     : "memory");
        asm volatile("cp.async.bulk.shared::cta.global.mbarrier::complete_tx::bytes "
                     "[%0], [%1], %2, [%3];"
                     :: "r"(tile_a + ATTR_BYTES), "l"(srcE), "r"((uint32_t)ENT_BYTES), "r"(mbar_a)
                     : "memory");
    }
    // all threads wait for completion (phase 0), acquire ordering
    {
        uint32_t done;
        asm volatile("{\n\t.reg .pred p;\n\t"
                     "mbarrier.try_wait.parity.acquire.cta.shared::cta.b64 p, [%1], 0;\n\t"
                     "selp.b32 %0, 1, 0, p;\n\t}"
                     : "=r"(done) : "r"(mbar_a) : "memory");
        if (!done) {
            asm volatile("{\n\t.reg .pred P1;\n\t"
                         "WL_%=:\n\t"
                         "mbarrier.try_wait.parity.acquire.cta.shared::cta.b64 P1, [%0], 0, 0x989680;\n\t"
                         "@P1 bra.uni WD_%=;\n\t"
                         "bra.uni WL_%=;\n\t"
                         "WD_%=:\n\t}"
                         :: "r"(mbar_a) : "memory");
        }
    }

    // ---- Pass 1: scores from SMEM (conflict-free LDS.128) ----------------
    const float4* a4  = reinterpret_cast<const float4*>(avec);   // [0,64)=a_attr, [64,128)=a_ent
    const float4 aa0 = __ldg(a4 + lane);
    const float4 aa1 = __ldg(a4 + 32 + lane);

    auto dot8 = [](const float4& x0, const float4& x1,
                   const float4& y0, const float4& y1) -> float {
        return x0.x*y0.x + x0.y*y0.y + x0.z*y0.z + x0.w*y0.w
             + x1.x*y1.x + x1.y*y1.y + x1.z*y1.z + x1.w*y1.w;
    };

    // Warp w owns rows a = w + 8k; k=0..5 always valid, k=6: a=48+w for w<3
    // (w==2 -> row 50 = entity row, dotted against a_ent).
    float p[7];
#pragma unroll
    for (int k = 0; k < 6; k++) {
        const int a = w + 8 * k;
        const float4 v0 = tile4[a * D4 + lane];
        const float4 v1 = tile4[a * D4 + 32 + lane];
        p[k] = dot8(v0, v1, aa0, aa1);
    }
    p[6] = 0.f;
    if (w < 3) {
        const int a = 48 + w;                    // 48, 49, 50(entity)
        const float4 v0 = tile4[a * D4 + lane];
        const float4 v1 = tile4[a * D4 + 32 + lane];
        if (w == 2) {
            const float4 ce0 = __ldg(a4 + 64 + lane);
            const float4 ce1 = __ldg(a4 + 96 + lane);
            p[6] = dot8(v0, v1, ce0, ce1);
        } else {
            p[6] = dot8(v0, v1, aa0, aa1);
        }
    }

    // Batched warp reductions: 7 independent values, 5 rounds
#pragma unroll
    for (int off = 16; off; off >>= 1) {
#pragma unroll
        for (int k = 0; k < 7; k++)
            p[k] += __shfl_xor_sync(0xffffffffu, p[k], off);
    }
    if (lane == 0) {
#pragma unroll
        for (int k = 0; k < 6; k++)
            e_s[w + 8 * k] = p[k];
        if (w < 3) e_s[48 + w] = p[6];           // slot 50 = entity bias
    }
    __syncthreads();

    // ---- Softmax over 50 scores (single warp) ----------------------------
    if (w == 0) {
        const float bias = e_s[An];
        float e0 = (lane      < An) ? e_s[lane]      + bias : -INFINITY;
        float e1 = (lane + 32 < An) ? e_s[lane + 32] + bias : -INFINITY;
        e0 = (e0 > 0.f) ? e0 : ALPHA * e0;       // leaky_relu; -inf stays -inf
        e1 = (e1 > 0.f) ? e1 : ALPHA * e1;

        float m = fmaxf(e0, e1);
#pragma unroll
        for (int off = 16; off; off >>= 1)
            m = fmaxf(m, __shfl_xor_sync(0xffffffffu, m, off));
        float q0 = __expf(e0 - m);               // exp(-inf)=0 for masked lanes
        float q1 = __expf(e1 - m);
        float s = q0 + q1;
#pragma unroll
        for (int off = 16; off; off >>= 1)
            s += __shfl_xor_sync(0xffffffffu, s, off);

        const float scale = (float)An / s;       // softmax * attr_num
        if (lane      < An) att_s[lane]      = q0 * scale;
        if (lane + 32 < An) att_s[lane + 32] = q1 * scale;
    }
    __syncthreads();

    // ---- Pass 2: out[b, d] = sum_a att[a] * tile[a, d] -------------------
    if (t < D4) {
        float4 acc = make_float4(0.f, 0.f, 0.f, 0.f);
#pragma unroll
        for (int a = 0; a < An; a++) {
            const float att = att_s[a];
            const float4 v  = tile4[a * D4 + t];
            acc.x = fmaf(att, v.x, acc.x);
            acc.y = fmaf(att, v.y, acc.y);
            acc.z = fmaf(att, v.z, acc.z);
            acc.w = fmaf(att, v.w, acc.w);
        }
        reinterpret_cast<float4*>(out)[(size_t)b * D4 + t] = acc;
    }
}

extern "C" void kernel_launch(void* const* d_in, const int* in_sizes, int n_in,
                              void* d_out, int out_size)
{
    const float* attrs = (const float*)d_in[0];   // [B, A, D] fp32
    const float* ent   = (const float*)d_in[1];   // [B, D]    fp32
    const float* avec  = (const float*)d_in[2];   // [2D, 1]   fp32
    float* out         = (float*)d_out;           // [B, D]    fp32

    cudaFuncSetAttribute(struct_attention_kernel,
                         cudaFuncAttributeMaxDynamicSharedMemorySize, SMEM_BYTES);

    struct_attention_kernel<<<Bn, NTHREADS, SMEM_BYTES>>>(attrs, ent, avec, out);
}